// round 14
// baseline (speedup 1.0000x reference)
#include <cuda_runtime.h>
#include <cuda_bf16.h>

// Problem constants (fixed by reference setup_inputs)
#define NB        4
#define CHN       256
#define FH        96
#define FW        96
#define PIX       (FH * FW)          // 9216
#define OUTS      7
#define SAMPLE    2
#define NBINS     (OUTS * OUTS)      // 49
#define SCALE     0.0625f
#define CHN4      (CHN / 4)          // 64 float4 per pixel

// Staging split: bins [0,32) at stride 33 (padded), bins [32,49) at stride 17.
#define P1BINS    32
#define P1STRIDE  33
#define P2BINS    17
#define P2STRIDE  17
#define SMEM_FLT  (P1STRIDE * CHN)   // 8448 floats = 33792 B (covers both phases)

// Scratch: features transposed to NHWC [n][y][x][c] for coalesced channel gathers.
__device__ float g_featT[(size_t)NB * PIX * CHN];   // 37.75 MB

// ---------------------------------------------------------------------------
// Pass 1: NCHW -> NHWC transpose, float4 both sides.
// ---------------------------------------------------------------------------
__global__ void __launch_bounds__(256) transpose_kernel(const float* __restrict__ in) {
    __shared__ float tile[32][33];
    const int n   = blockIdx.z;
    const int p0  = blockIdx.x * 32;   // pixel tile
    const int c0  = blockIdx.y * 32;   // channel tile
    const int tid = threadIdx.x;

    {   // read: c = tid>>3 (0..31), q = tid&7 (pixel quad)
        const int c = tid >> 3, q = tid & 7;
        const float4 v = *(const float4*)(in + (size_t)n * CHN * PIX
                                             + (size_t)(c0 + c) * PIX + p0 + q * 4);
        tile[c][q * 4 + 0] = v.x;
        tile[c][q * 4 + 1] = v.y;
        tile[c][q * 4 + 2] = v.z;
        tile[c][q * 4 + 3] = v.w;
    }
    __syncthreads();
    {   // write: p = tid>>3 (0..31), qc = tid&7 (channel quad)
        const int p = tid >> 3, qc = tid & 7;
        float4 o;
        o.x = tile[qc * 4 + 0][p];
        o.y = tile[qc * 4 + 1][p];
        o.z = tile[qc * 4 + 2][p];
        o.w = tile[qc * 4 + 3][p];
        *(float4*)(g_featT + (size_t)n * PIX * CHN
                           + (size_t)(p0 + p) * CHN + c0 + qc * 4) = o;
    }
}

// ---------------------------------------------------------------------------
// Pass 2: one CTA per roi. Per-bin collapsed weights:
//   out[ph][pw] = sum_r cwy[ph][r] * sum_c cwx[pw][c] * feat[r][c]
// (duplicate taps from the 2x2 samples pre-merged; validity and the 0.25
// sample-mean folded into the separable 1-D weights). 256 threads = 64
// float4-channel groups x 4 bin groups. Output staged in smem in TWO phases
// (bins 0-31, then 32-48) to keep dynamic smem at 33.8 KB -> 6 CTAs/SM.
// ---------------------------------------------------------------------------
__global__ void __launch_bounds__(256) roialign_kernel(const float* __restrict__ rois,
                                                       float* __restrict__ out) {
    extern __shared__ float s_out[];          // SMEM_FLT floats (33792 B)
    __shared__ int   s_rn[OUTS];              // rows per bin-row
    __shared__ int   s_prow[OUTS][4];         // row * FW (premultiplied)
    __shared__ float s_rw[OUTS][4];           // collapsed y-weights (x0.25 folded)
    __shared__ int   s_cn[OUTS];              // cols per bin-col
    __shared__ int   s_pcol[OUTS][4];
    __shared__ float s_cw[OUTS][4];           // collapsed x-weights
    __shared__ float s_roi[5];

    const int k   = blockIdx.x;
    const int tid = threadIdx.x;
    const int cg  = tid & 63;         // channel group: channels cg*4 .. cg*4+3
    const int bg  = tid >> 6;         // bin group: bins bg, bg+4, bg+8, ...
    const int c0  = cg * 4;

    if (tid < 5) s_roi[tid] = rois[k * 5 + tid];
    __syncthreads();

    const int   n  = (int)s_roi[0];
    const float x1 = s_roi[1] * SCALE;
    const float y1 = s_roi[2] * SCALE;
    const float x2 = s_roi[3] * SCALE;
    const float y2 = s_roi[4] * SCALE;
    const float bin_w = fmaxf(x2 - x1, 1.0f) * (1.0f / OUTS);
    const float bin_h = fmaxf(y2 - y1, 1.0f) * (1.0f / OUTS);

    // Build per-bin collapsed tap tables. Thread t<7: bin-row t (y axis);
    // thread 8..14: bin-col t-8 (x axis).
    if (tid < 16 && (tid & 7) < 7) {
        const bool isx  = tid >= 8;
        const int  bi   = tid & 7;            // ph or pw
        const float start = isx ? x1 : y1;
        const float bs    = isx ? bin_w : bin_h;
        const float size  = 96.0f;

        int   tv[4];
        float tw[4];
#pragma unroll
        for (int s = 0; s < 2; s++) {
            const float off   = (float)bi + ((float)s + 0.5f) * 0.5f;
            const float coord = start + bs * off;
            const float valid = (coord >= -1.0f && coord <= size) ? 1.0f : 0.0f;
            const float c  = fminf(fmaxf(coord, 0.0f), size - 1.0f);
            const float lo = floorf(c);
            const float hi = fminf(lo + 1.0f, size - 1.0f);
            const float fr = c - lo;
            tv[2 * s + 0] = (int)lo; tw[2 * s + 0] = (1.0f - fr) * valid;
            tv[2 * s + 1] = (int)hi; tw[2 * s + 1] = fr * valid;
        }
        // merge duplicate tap positions
        int   mv[4]; float mw[4]; int nm = 0;
#pragma unroll
        for (int i = 0; i < 4; i++) {
            bool found = false;
#pragma unroll
            for (int j = 0; j < 4; j++) {
                if (j < nm && mv[j] == tv[i]) { mw[j] += tw[i]; found = true; }
            }
            if (!found) { mv[nm] = tv[i]; mw[nm] = tw[i]; nm++; }
        }
        if (isx) {
            s_cn[bi] = nm;
#pragma unroll
            for (int j = 0; j < 4; j++) {
                s_pcol[bi][j] = (j < nm) ? mv[j] : 0;
                s_cw[bi][j]   = (j < nm) ? mw[j] : 0.0f;
            }
        } else {
            s_rn[bi] = nm;
#pragma unroll
            for (int j = 0; j < 4; j++) {
                s_prow[bi][j] = (j < nm) ? mv[j] * FW : 0;
                s_rw[bi][j]   = (j < nm) ? mw[j] * 0.25f : 0.0f;  // fold sample mean
            }
        }
    }
    __syncthreads();

    // float4 gather base: warp reads 512B contiguous per tap.
    const float4* feat4 = (const float4*)g_featT + (size_t)n * PIX * CHN4 + cg;
    float* o = out + (size_t)k * NBINS * CHN;

    // ---- Phase 1: bins [0, 32) ----
    for (int b = bg; b < P1BINS; b += 4) {
        const int ph = b / OUTS;
        const int pw = b - ph * OUTS;
        const int rn = s_rn[ph];
        const int cn = s_cn[pw];
        float4 acc = make_float4(0.f, 0.f, 0.f, 0.f);
#pragma unroll 4
        for (int ri = 0; ri < rn; ri++) {
            const int   rb = s_prow[ph][ri];
            const float wy = s_rw[ph][ri];
            float4 tmp = make_float4(0.f, 0.f, 0.f, 0.f);
#pragma unroll 4
            for (int ci = 0; ci < cn; ci++) {
                const float4 t  = feat4[(size_t)(rb + s_pcol[pw][ci]) * CHN4];
                const float  wx = s_cw[pw][ci];
                tmp.x += t.x * wx; tmp.y += t.y * wx;
                tmp.z += t.z * wx; tmp.w += t.w * wx;
            }
            acc.x += tmp.x * wy; acc.y += tmp.y * wy;
            acc.z += tmp.z * wy; acc.w += tmp.w * wy;
        }
        s_out[(c0 + 0) * P1STRIDE + b] = acc.x;
        s_out[(c0 + 1) * P1STRIDE + b] = acc.y;
        s_out[(c0 + 2) * P1STRIDE + b] = acc.z;
        s_out[(c0 + 3) * P1STRIDE + b] = acc.w;
    }
    __syncthreads();
    // copy out bins [0,32): i -> c = i/32, b = i%32; smem conflict-free,
    // gmem writes in 128B-contiguous runs per channel.
    for (int i = tid; i < P1BINS * CHN; i += 256) {
        const int c = i >> 5, b = i & 31;
        o[c * NBINS + b] = s_out[c * P1STRIDE + b];
    }
    __syncthreads();

    // ---- Phase 2: bins [32, 49) ----
    for (int b = P1BINS + bg; b < NBINS; b += 4) {
        const int ph = b / OUTS;
        const int pw = b - ph * OUTS;
        const int rn = s_rn[ph];
        const int cn = s_cn[pw];
        float4 acc = make_float4(0.f, 0.f, 0.f, 0.f);
#pragma unroll 4
        for (int ri = 0; ri < rn; ri++) {
            const int   rb = s_prow[ph][ri];
            const float wy = s_rw[ph][ri];
            float4 tmp = make_float4(0.f, 0.f, 0.f, 0.f);
#pragma unroll 4
            for (int ci = 0; ci < cn; ci++) {
                const float4 t  = feat4[(size_t)(rb + s_pcol[pw][ci]) * CHN4];
                const float  wx = s_cw[pw][ci];
                tmp.x += t.x * wx; tmp.y += t.y * wx;
                tmp.z += t.z * wx; tmp.w += t.w * wx;
            }
            acc.x += tmp.x * wy; acc.y += tmp.y * wy;
            acc.z += tmp.z * wy; acc.w += tmp.w * wy;
        }
        const int bb = b - P1BINS;
        s_out[(c0 + 0) * P2STRIDE + bb] = acc.x;
        s_out[(c0 + 1) * P2STRIDE + bb] = acc.y;
        s_out[(c0 + 2) * P2STRIDE + bb] = acc.z;
        s_out[(c0 + 3) * P2STRIDE + bb] = acc.w;
    }
    __syncthreads();
    // copy out bins [32,49): addr == i on smem side (conflict-free).
    for (int i = tid; i < P2BINS * CHN; i += 256) {
        const int c = i / P2STRIDE, b = i - c * P2STRIDE;
        o[c * NBINS + P1BINS + b] = s_out[i];
    }
}

extern "C" void kernel_launch(void* const* d_in, const int* in_sizes, int n_in,
                              void* d_out, int out_size) {
    const float* features = (const float*)d_in[0];
    const float* rois     = (const float*)d_in[1];
    float*       out      = (float*)d_out;

    const int K = in_sizes[1] / 5;
    const int smem = SMEM_FLT * (int)sizeof(float);   // 33792 B

    cudaFuncSetAttribute(roialign_kernel,
                         cudaFuncAttributeMaxDynamicSharedMemorySize, smem);

    dim3 tgrid(PIX / 32, CHN / 32, NB);
    transpose_kernel<<<tgrid, 256>>>(features);

    roialign_kernel<<<K, 256, smem>>>(rois, out);
}

// round 17
// speedup vs baseline: 1.1741x; 1.1741x over previous
#include <cuda_runtime.h>
#include <cuda_bf16.h>

// Problem constants (fixed by reference setup_inputs)
#define NB        4
#define CHN       256
#define FH        96
#define FW        96
#define PIX       (FH * FW)          // 9216
#define OUTS      7
#define NBINS     (OUTS * OUTS)      // 49
#define SCALE     0.0625f
#define CHN4      (CHN / 4)          // 64 float4 per pixel

// Three staging phases of 17/17/15 bins at stride 17 -> 17408 B dynamic smem.
#define PSTRIDE   17
#define SMEM_FLT  (PSTRIDE * CHN)    // 4352 floats = 17408 B

// Scratch: features transposed to NHWC [n][y][x][c] for coalesced channel gathers.
__device__ float g_featT[(size_t)NB * PIX * CHN];   // 37.75 MB

// ---------------------------------------------------------------------------
// Pass 1: NCHW -> NHWC transpose, float4 both sides.
// ---------------------------------------------------------------------------
__global__ void __launch_bounds__(256) transpose_kernel(const float* __restrict__ in) {
    __shared__ float tile[32][33];
    const int n   = blockIdx.z;
    const int p0  = blockIdx.x * 32;   // pixel tile
    const int c0  = blockIdx.y * 32;   // channel tile
    const int tid = threadIdx.x;

    {   // read: c = tid>>3 (0..31), q = tid&7 (pixel quad)
        const int c = tid >> 3, q = tid & 7;
        const float4 v = *(const float4*)(in + (size_t)n * CHN * PIX
                                             + (size_t)(c0 + c) * PIX + p0 + q * 4);
        tile[c][q * 4 + 0] = v.x;
        tile[c][q * 4 + 1] = v.y;
        tile[c][q * 4 + 2] = v.z;
        tile[c][q * 4 + 3] = v.w;
    }
    __syncthreads();
    {   // write: p = tid>>3 (0..31), qc = tid&7 (channel quad)
        const int p = tid >> 3, qc = tid & 7;
        float4 o;
        o.x = tile[qc * 4 + 0][p];
        o.y = tile[qc * 4 + 1][p];
        o.z = tile[qc * 4 + 2][p];
        o.w = tile[qc * 4 + 3][p];
        *(float4*)(g_featT + (size_t)n * PIX * CHN
                           + (size_t)(p0 + p) * CHN + c0 + qc * 4) = o;
    }
}

// ---------------------------------------------------------------------------
// Pass 2: one CTA per roi. FLAT per-bin tap tables:
//   each bin holds <=16 (offset, weight) pairs, offset = (row*FW+col)*CHN4,
//   weight = wy*wx with duplicate taps merged, validity + 0.25 mean folded,
//   zero-weight taps dropped. Mainloop is one flat loop per bin:
//   LDS.64 + IMAD + LDG.128 + 4xFFMA per tap (minimal issue count).
// 256 threads = 64 float4-channel groups x 4 bin groups. Output staged in
// smem in THREE phases (17/17/15 bins) -> 17.4 KB dynamic -> 8 CTAs/SM,
// whole 1024-CTA grid resident in a single wave.
// ---------------------------------------------------------------------------
__global__ void __launch_bounds__(256) roialign_kernel(const float* __restrict__ rois,
                                                       float* __restrict__ out) {
    extern __shared__ float s_out[];          // SMEM_FLT floats (17408 B)
    __shared__ int   s_rn[OUTS];              // rows per bin-row (axis build)
    __shared__ int   s_prow[OUTS][4];         // row * FW
    __shared__ float s_rw[OUTS][4];           // collapsed y-weights (x0.25 folded)
    __shared__ int   s_cn[OUTS];              // cols per bin-col
    __shared__ int   s_pcol[OUTS][4];
    __shared__ float s_cw[OUTS][4];           // collapsed x-weights
    __shared__ int2  s_tap[NBINS][16];        // flat taps: x=elem offset, y=weight bits
    __shared__ int   s_tn[NBINS];             // taps per bin
    __shared__ float s_roi[5];

    const int k   = blockIdx.x;
    const int tid = threadIdx.x;
    const int cg  = tid & 63;         // channel group: channels cg*4 .. cg*4+3
    const int bg  = tid >> 6;         // bin group
    const int c0  = cg * 4;

    if (tid < 5) s_roi[tid] = rois[k * 5 + tid];
    __syncthreads();

    const int   n  = (int)s_roi[0];
    const float x1 = s_roi[1] * SCALE;
    const float y1 = s_roi[2] * SCALE;
    const float x2 = s_roi[3] * SCALE;
    const float y2 = s_roi[4] * SCALE;
    const float bin_w = fmaxf(x2 - x1, 1.0f) * (1.0f / OUTS);
    const float bin_h = fmaxf(y2 - y1, 1.0f) * (1.0f / OUTS);

    // Axis build: thread t<7 -> bin-row t (y); threads 8..14 -> bin-col t-8 (x).
    if (tid < 16 && (tid & 7) < 7) {
        const bool isx  = tid >= 8;
        const int  bi   = tid & 7;
        const float start = isx ? x1 : y1;
        const float bs    = isx ? bin_w : bin_h;
        const float size  = 96.0f;

        int   tv[4];
        float tw[4];
#pragma unroll
        for (int s = 0; s < 2; s++) {
            const float off   = (float)bi + ((float)s + 0.5f) * 0.5f;
            const float coord = start + bs * off;
            const float valid = (coord >= -1.0f && coord <= size) ? 1.0f : 0.0f;
            const float c  = fminf(fmaxf(coord, 0.0f), size - 1.0f);
            const float lo = floorf(c);
            const float hi = fminf(lo + 1.0f, size - 1.0f);
            const float fr = c - lo;
            tv[2 * s + 0] = (int)lo; tw[2 * s + 0] = (1.0f - fr) * valid;
            tv[2 * s + 1] = (int)hi; tw[2 * s + 1] = fr * valid;
        }
        // merge duplicate tap positions
        int   mv[4]; float mw[4]; int nm = 0;
#pragma unroll
        for (int i = 0; i < 4; i++) {
            bool found = false;
#pragma unroll
            for (int j = 0; j < 4; j++) {
                if (j < nm && mv[j] == tv[i]) { mw[j] += tw[i]; found = true; }
            }
            if (!found) { mv[nm] = tv[i]; mw[nm] = tw[i]; nm++; }
        }
        if (isx) {
            s_cn[bi] = nm;
#pragma unroll
            for (int j = 0; j < 4; j++) {
                s_pcol[bi][j] = (j < nm) ? mv[j] : 0;
                s_cw[bi][j]   = (j < nm) ? mw[j] : 0.0f;
            }
        } else {
            s_rn[bi] = nm;
#pragma unroll
            for (int j = 0; j < 4; j++) {
                s_prow[bi][j] = (j < nm) ? mv[j] * FW : 0;
                s_rw[bi][j]   = (j < nm) ? mw[j] * 0.25f : 0.0f;  // fold sample mean
            }
        }
    }
    __syncthreads();

    // Flat tap build: one thread per bin computes the row x col cross product.
    if (tid < NBINS) {
        const int ph = tid / OUTS, pw = tid - (tid / OUTS) * OUTS;
        const int rn = s_rn[ph], cn = s_cn[pw];
        int nt = 0;
        for (int ri = 0; ri < rn; ri++) {
            const int   pr = s_prow[ph][ri];
            const float wy = s_rw[ph][ri];
            for (int ci = 0; ci < cn; ci++) {
                const float w = wy * s_cw[pw][ci];
                if (w != 0.0f) {
                    s_tap[tid][nt] = make_int2((pr + s_pcol[pw][ci]) * CHN4,
                                               __float_as_int(w));
                    nt++;
                }
            }
        }
        s_tn[tid] = nt;
    }
    __syncthreads();

    // float4 gather base: warp reads 512B contiguous per tap.
    const float4* feat4 = (const float4*)g_featT + (size_t)n * PIX * CHN4 + cg;
    float* o = out + (size_t)k * NBINS * CHN;

#pragma unroll
    for (int p = 0; p < 3; p++) {
        const int start = p * PSTRIDE;
        const int L = (p == 2) ? (NBINS - 2 * PSTRIDE) : PSTRIDE;   // 17,17,15

        for (int b = start + bg; b < start + L; b += 4) {
            const int  nt  = s_tn[b];
            const int2* tap = s_tap[b];
            float4 acc = make_float4(0.f, 0.f, 0.f, 0.f);
#pragma unroll 4
            for (int i = 0; i < nt; i++) {
                const int2  t = tap[i];               // broadcast LDS.64
                const float w = __int_as_float(t.y);
                const float4 v = feat4[t.x];
                acc.x += v.x * w; acc.y += v.y * w;
                acc.z += v.z * w; acc.w += v.w * w;
            }
            const int lb = b - start;
            s_out[(c0 + 0) * PSTRIDE + lb] = acc.x;
            s_out[(c0 + 1) * PSTRIDE + lb] = acc.y;
            s_out[(c0 + 2) * PSTRIDE + lb] = acc.z;
            s_out[(c0 + 3) * PSTRIDE + lb] = acc.w;
        }
        __syncthreads();
        // copy out this phase: smem side conflict-free (consecutive within a
        // channel's run), gmem side runs of L floats per channel.
        for (int i = tid; i < L * CHN; i += 256) {
            const int c = i / L, lb = i - c * L;
            o[c * NBINS + start + lb] = s_out[c * PSTRIDE + lb];
        }
        __syncthreads();
    }
}

extern "C" void kernel_launch(void* const* d_in, const int* in_sizes, int n_in,
                              void* d_out, int out_size) {
    const float* features = (const float*)d_in[0];
    const float* rois     = (const float*)d_in[1];
    float*       out      = (float*)d_out;

    const int K = in_sizes[1] / 5;
    const int smem = SMEM_FLT * (int)sizeof(float);   // 17408 B

    cudaFuncSetAttribute(roialign_kernel,
                         cudaFuncAttributeMaxDynamicSharedMemorySize, smem);

    dim3 tgrid(PIX / 32, CHN / 32, NB);
    transpose_kernel<<<tgrid, 256>>>(features);

    roialign_kernel<<<K, 256, smem>>>(rois, out);
}